// round 2
// baseline (speedup 1.0000x reference)
#include <cuda_runtime.h>
#include <cuda_bf16.h>

#define BB 512
#define SS 1024
#define TT 48

// Scratch (no device allocation allowed -> __device__ globals)
__device__ float g_logZ[BB];
__device__ float g_gold[BB];

// ---------------------------------------------------------------------------
// Forward algorithm: 48 threads per batch, 2 batches per 96-thread block.
// Thread j owns state j; holds E[:,j] = exp(trans[:,j]) in registers.
// score kept normalized: s_j = true_score_j - c; c accumulates log(sum p).
// ---------------------------------------------------------------------------
__global__ void __launch_bounds__(96) crf_forward(
    const float* __restrict__ em,       // [B,S,T]
    const float* __restrict__ trans,    // [T,T]
    const float* __restrict__ startt,   // [T]
    const float* __restrict__ endt,     // [T]
    const int* __restrict__ mask)       // [B,S] bool stored as int32
{
    // p buffers: per batch-slot stride 112 floats (bank-shift), double buffered 48 each
    __shared__ float p_sh[2 * 112];

    const int tid   = threadIdx.x;
    const int bslot = tid / 48;        // 0 or 1
    const int j     = tid - bslot * 48;
    const int b     = blockIdx.x * 2 + bslot;
    const int base  = bslot * 112;

    // E column j in registers (48 regs)
    float E[TT];
#pragma unroll
    for (int i = 0; i < TT; i++) E[i] = __expf(trans[i * TT + j]);

    const float* emb = em + (size_t)b * SS * TT;
    const int* mk = mask + (size_t)b * SS;

    float s = startt[j] + emb[j];
    float c = 0.0f;
    int buf = 0;

    // software-pipelined loads for step t=1
    float e_next = emb[TT + j];
    int m_next = mk[1];

    for (int t = 1; t < SS; t++) {
        float p = __expf(s);
        p_sh[base + buf * 48 + j] = p;
        float e_cur = e_next;
        int m_cur = m_next;
        __syncthreads();

        // prefetch next step's emission/mask to overlap LDG with the FMA loop
        if (t + 1 < SS) {
            e_next = emb[(t + 1) * TT + j];
            m_next = mk[t + 1];
        }

        const float4* pv = (const float4*)(p_sh + base + buf * 48);
        float acc = 0.0f, ssum = 0.0f;
#pragma unroll
        for (int q = 0; q < 12; q++) {
            float4 v = pv[q];
            acc  = fmaf(v.x, E[4 * q + 0], acc);
            acc  = fmaf(v.y, E[4 * q + 1], acc);
            acc  = fmaf(v.z, E[4 * q + 2], acc);
            acc  = fmaf(v.w, E[4 * q + 3], acc);
            ssum += (v.x + v.y) + (v.z + v.w);
        }

        float la = __logf(acc);
        float ls = __logf(ssum);
        if (m_cur) {
            s = la - ls + e_cur;   // normalized new score
            c += ls;               // accumulated normalization
        }
        buf ^= 1;
    }

    // final logsumexp with end_transitions
    float v = __expf(s + endt[j]);
    __syncthreads();               // last loop reads must finish before overwrite
    p_sh[base + j] = v;
    __syncthreads();
    if (j == 0) {
        float sum = 0.0f;
#pragma unroll
        for (int i = 0; i < TT; i++) sum += p_sh[base + i];
        g_logZ[b] = c + __logf(sum);
    }
}

// ---------------------------------------------------------------------------
// Gold path score: one block (128 threads) per batch
// ---------------------------------------------------------------------------
__global__ void __launch_bounds__(128) crf_gold(
    const float* __restrict__ em,
    const float* __restrict__ trans,
    const float* __restrict__ startt,
    const float* __restrict__ endt,
    const int* __restrict__ tags,
    const int* __restrict__ mask)
{
    const int b = blockIdx.x;
    const int tid = threadIdx.x;
    const int* tg = tags + (size_t)b * SS;
    const int* mk = mask + (size_t)b * SS;
    const float* emb = em + (size_t)b * SS * TT;

    float local = 0.0f;
    int cnt = 0;
    for (int t = tid; t < SS; t += 128) {
        int tt = tg[t];
        if (mk[t]) cnt++;
        if (t == 0) {
            local += startt[tt] + emb[tt];
        } else if (mk[t]) {
            local += trans[tg[t - 1] * TT + tt] + emb[t * TT + tt];
        }
    }

    __shared__ float rs[128];
    __shared__ int   ri[128];
    rs[tid] = local;
    ri[tid] = cnt;
    __syncthreads();
    for (int off = 64; off > 0; off >>= 1) {
        if (tid < off) { rs[tid] += rs[tid + off]; ri[tid] += ri[tid + off]; }
        __syncthreads();
    }
    if (tid == 0) {
        int len = ri[0] - 1;            // lengths = sum(mask) - 1
        g_gold[b] = rs[0] + endt[tg[len]];
    }
}

// ---------------------------------------------------------------------------
// Final mean(logZ - gold)
// ---------------------------------------------------------------------------
__global__ void __launch_bounds__(512) crf_reduce(float* __restrict__ out)
{
    __shared__ float rs[512];
    const int tid = threadIdx.x;
    rs[tid] = g_logZ[tid] - g_gold[tid];
    __syncthreads();
    for (int off = 256; off > 0; off >>= 1) {
        if (tid < off) rs[tid] += rs[tid + off];
        __syncthreads();
    }
    if (tid == 0) out[0] = rs[0] / (float)BB;
}

extern "C" void kernel_launch(void* const* d_in, const int* in_sizes, int n_in,
                              void* d_out, int out_size)
{
    const float* em    = (const float*)d_in[0];
    const float* tr    = (const float*)d_in[1];
    const float* st    = (const float*)d_in[2];
    const float* en    = (const float*)d_in[3];
    const int*   tags  = (const int*)d_in[4];
    const int*   mask  = (const int*)d_in[5];
    float* out = (float*)d_out;

    crf_gold<<<BB, 128>>>(em, tr, st, en, tags, mask);
    crf_forward<<<BB / 2, 96>>>(em, tr, st, en, mask);
    crf_reduce<<<1, 512>>>(out);
}